// round 6
// baseline (speedup 1.0000x reference)
#include <cuda_runtime.h>
#include <math.h>

#define Bq   4
#define Sq   2048
#define Dq   512
#define Hq   8
#define DKq  64
#define KN   9
#define BHq  32
#define Mq   8192   /* B*S */
#define EPSN 1e-12f

typedef unsigned long long ull;

// ---------------- packed fp32x2 helpers (sm_103a FFMA2) ----------------
__device__ __forceinline__ ull pack2(float x) {
    ull r;
    asm("mov.b64 %0, {%1, %1};" : "=l"(r) : "f"(x));
    return r;
}
__device__ __forceinline__ void fma2(ull& d, ull a, ull b) {
    asm("fma.rn.f32x2 %0, %1, %2, %0;" : "+l"(d) : "l"(a), "l"(b));
}
__device__ __forceinline__ float lo32(ull v) {
    return __uint_as_float((unsigned)v);
}
__device__ __forceinline__ float hi32(ull v) {
    return __uint_as_float((unsigned)(v >> 32));
}

// ---------------- scratch (device globals; no allocation) ----------------
__device__ float g_q[BHq * Sq * DKq];      // [bh][s][c]
__device__ float g_k[BHq * Sq * DKq];
__device__ float g_v[BHq * Sq * DKq];
__device__ int   g_idx[BHq * Sq * KN];     // top-9 indices, sorted desc by sim
__device__ float g_y[Dq * Mq];             // y^T: [col][b*S + s']
__device__ float g_wt[KN * DKq * DKq];     // Wt[kk][c][o]

// ---------------- Kernel A: QKV GEMM  out = x @ W^T + b, split-head layout ----
// (round-4 version: pipelined, non-duplicated B)
__global__ __launch_bounds__(256, 2) void qkv_gemm_kernel(
    const float* __restrict__ x,
    const float* __restrict__ Wq, const float* __restrict__ bq,
    const float* __restrict__ Wk, const float* __restrict__ bk,
    const float* __restrict__ Wv, const float* __restrict__ bv)
{
    __shared__ __align__(16) float As[16][132];
    __shared__ __align__(16) float Bs[16][132];

    const float* W; const float* bias; float* out;
    int z = blockIdx.z;
    if (z == 0)      { W = Wq; bias = bq; out = g_q; }
    else if (z == 1) { W = Wk; bias = bk; out = g_k; }
    else             { W = Wv; bias = bv; out = g_v; }

    int m0 = blockIdx.y * 128;
    int n0 = blockIdx.x * 128;
    int tid = threadIdx.x;
    int tx = tid & 15, ty = tid >> 4;
    int r0 = ty * 8, c0 = tx * 8;

    ull acc[4][8];
#pragma unroll
    for (int i = 0; i < 4; i++)
#pragma unroll
        for (int j = 0; j < 8; j++) acc[i][j] = 0ULL;

    int lrow = tid >> 2;
    int lk   = (tid & 3) * 4;

    const float* pa0 = x + (size_t)(m0 + lrow)      * 512 + lk;
    const float* pa1 = x + (size_t)(m0 + lrow + 64) * 512 + lk;
    const float* pb0 = W + (size_t)(n0 + lrow)      * 512 + lk;
    const float* pb1 = W + (size_t)(n0 + lrow + 64) * 512 + lk;

    float4 a0 = *(const float4*)(pa0);
    float4 a1 = *(const float4*)(pa1);
    float4 b0 = *(const float4*)(pb0);
    float4 b1 = *(const float4*)(pb1);

    for (int k0 = 0; k0 < 512; k0 += 16) {
        __syncthreads();
        As[lk+0][lrow] = a0.x; As[lk+1][lrow] = a0.y; As[lk+2][lrow] = a0.z; As[lk+3][lrow] = a0.w;
        As[lk+0][lrow+64] = a1.x; As[lk+1][lrow+64] = a1.y; As[lk+2][lrow+64] = a1.z; As[lk+3][lrow+64] = a1.w;
        Bs[lk+0][lrow] = b0.x; Bs[lk+1][lrow] = b0.y; Bs[lk+2][lrow] = b0.z; Bs[lk+3][lrow] = b0.w;
        Bs[lk+0][lrow+64] = b1.x; Bs[lk+1][lrow+64] = b1.y; Bs[lk+2][lrow+64] = b1.z; Bs[lk+3][lrow+64] = b1.w;
        __syncthreads();
        if (k0 + 16 < 512) {
            a0 = *(const float4*)(pa0 + k0 + 16);
            a1 = *(const float4*)(pa1 + k0 + 16);
            b0 = *(const float4*)(pb0 + k0 + 16);
            b1 = *(const float4*)(pb1 + k0 + 16);
        }
#pragma unroll
        for (int kk = 0; kk < 16; kk++) {
            ulonglong2 ap0 = *(const ulonglong2*)&As[kk][r0];
            ulonglong2 ap1 = *(const ulonglong2*)&As[kk][r0 + 4];
            float4 bv0 = *(const float4*)&Bs[kk][c0];
            float4 bv1 = *(const float4*)&Bs[kk][c0 + 4];
            ull b2[8];
            b2[0] = pack2(bv0.x); b2[1] = pack2(bv0.y); b2[2] = pack2(bv0.z); b2[3] = pack2(bv0.w);
            b2[4] = pack2(bv1.x); b2[5] = pack2(bv1.y); b2[6] = pack2(bv1.z); b2[7] = pack2(bv1.w);
            ull a2[4] = {ap0.x, ap0.y, ap1.x, ap1.y};
#pragma unroll
            for (int i = 0; i < 4; i++)
#pragma unroll
                for (int j = 0; j < 8; j++) fma2(acc[i][j], a2[i], b2[j]);
        }
    }

    float4 bias0 = *(const float4*)(bias + n0 + c0);
    float4 bias1 = *(const float4*)(bias + n0 + c0 + 4);
    int n = n0 + c0;
    int h = n >> 6, c = n & 63;
#pragma unroll
    for (int i = 0; i < 4; i++) {
#pragma unroll
        for (int half = 0; half < 2; half++) {
            int m = m0 + r0 + 2 * i + half;
            int bb = m >> 11;
            int s  = m & 2047;
            float4 o0, o1;
            if (half == 0) {
                o0.x = lo32(acc[i][0]) + bias0.x; o0.y = lo32(acc[i][1]) + bias0.y;
                o0.z = lo32(acc[i][2]) + bias0.z; o0.w = lo32(acc[i][3]) + bias0.w;
                o1.x = lo32(acc[i][4]) + bias1.x; o1.y = lo32(acc[i][5]) + bias1.y;
                o1.z = lo32(acc[i][6]) + bias1.z; o1.w = lo32(acc[i][7]) + bias1.w;
            } else {
                o0.x = hi32(acc[i][0]) + bias0.x; o0.y = hi32(acc[i][1]) + bias0.y;
                o0.z = hi32(acc[i][2]) + bias0.z; o0.w = hi32(acc[i][3]) + bias0.w;
                o1.x = hi32(acc[i][4]) + bias1.x; o1.y = hi32(acc[i][5]) + bias1.y;
                o1.z = hi32(acc[i][6]) + bias1.z; o1.w = hi32(acc[i][7]) + bias1.w;
            }
            float* po = out + ((size_t)(bb * Hq + h) * Sq + s) * DKq + c;
            *(float4*)po = o0;
            *(float4*)(po + 4) = o1;
        }
    }
}

// ---------------- Kernel B: L2-normalize q and k rows (over dk=64) ----------
__global__ __launch_bounds__(256) void normalize_kernel()
{
    int gw   = blockIdx.x * 8 + (threadIdx.x >> 5);
    int lane = threadIdx.x & 31;
    float* p;
    if (gw < BHq * Sq) p = g_k + (size_t)gw * 64;
    else               p = g_q + (size_t)(gw - BHq * Sq) * 64;
    float v0 = p[lane], v1 = p[lane + 32];
    float ss = v0 * v0 + v1 * v1;
#pragma unroll
    for (int o = 16; o; o >>= 1) ss += __shfl_xor_sync(0xffffffffu, ss, o);
    float inv = 1.0f / fmaxf(sqrtf(ss), EPSN);
    p[lane] = v0 * inv; p[lane + 32] = v1 * inv;
}

// ---------------- Kernel C: fused sim GEMM + ReLU + streaming top-9 ---------
// 512 threads, 2 blocks/SM (32 warps). Tile: 128 kn rows x 64 qn cols.
// Microtile: 8 rows x 2 cols per thread; A-operand is warp-broadcast.
__global__ __launch_bounds__(512, 2) void sim_topk_kernel()
{
    extern __shared__ __align__(16) float sm[];
    float* As = sm;              // 64*128 = 8192 floats
    float* Bs = sm + 8192;       // 64*64  = 4096 floats
    float* Ss = sm + 12288;      // 128*68 = 8704 floats

    int bh = blockIdx.y;
    int i0 = blockIdx.x * 128;
    int tid = threadIdx.x;
    int cx = tid & 31;           // col-pair id within 64 cols
    int ty = tid >> 5;           // warp id = row-group (constant per warp!)
    int r0 = ty * 8, c0 = cx * 2;

    const float* kbase = g_k + (size_t)bh * Sq * DKq;
    const float* qbase = g_q + (size_t)bh * Sq * DKq;

    // fill As (kn tile, transposed + swizzled), once: 4 float4 per thread
#pragma unroll
    for (int p = 0; p < 4; p++) {
        int f = tid + 512 * p;
        int r = f >> 4, dq = (f & 15) * 4;
        float4 v = *(const float4*)(kbase + (size_t)(i0 + r) * 64 + dq);
        int pr = r ^ (((dq >> 2) & 7) << 3);
        As[(dq + 0) * 128 + pr] = v.x;
        As[(dq + 1) * 128 + pr] = v.y;
        As[(dq + 2) * 128 + pr] = v.z;
        As[(dq + 3) * 128 + pr] = v.w;
    }

    float tv[9]; int ti[9];
#pragma unroll
    for (int q = 0; q < 9; q++) { tv[q] = -1.0f; ti[q] = 0; }

    int row = tid >> 2, part = tid & 3;   // 4 threads per row, 16 cols each
    int brow = tid >> 4, bdq = (tid & 15) * 4;
    const float* bptr = qbase + (size_t)brow * 64 + bdq;
    int sB = ((bdq >> 2) & 7) << 3;

    // prefetch first Bs tile: 2 float4 per thread (rows brow, brow+32)
    float4 br[2];
#pragma unroll
    for (int p = 0; p < 2; p++)
        br[p] = *(const float4*)(bptr + (size_t)(32 * p) * 64);

    for (int j0 = 0; j0 < Sq; j0 += 64) {
        __syncthreads();
        // store staged Bs tile (transposed + swizzled on j index)
#pragma unroll
        for (int p = 0; p < 2; p++) {
            int jp = (brow + 32 * p) ^ sB;
            Bs[(bdq + 0) * 64 + jp] = br[p].x;
            Bs[(bdq + 1) * 64 + jp] = br[p].y;
            Bs[(bdq + 2) * 64 + jp] = br[p].z;
            Bs[(bdq + 3) * 64 + jp] = br[p].w;
        }
        __syncthreads();
        // prefetch next Bs tile
        if (j0 + 64 < Sq) {
#pragma unroll
            for (int p = 0; p < 2; p++)
                br[p] = *(const float4*)(bptr + (size_t)(j0 + 64 + 32 * p) * 64);
        }

        ull acc[4][2];
#pragma unroll
        for (int i = 0; i < 4; i++) { acc[i][0] = 0ULL; acc[i][1] = 0ULL; }

#pragma unroll 8
        for (int kk = 0; kk < 64; kk++) {
            int swz = ((kk >> 2) & 7) << 3;
            // A: rows r0..r0+7 as 4 packed pairs — same address across warp (broadcast)
            ulonglong2 ap0 = *(const ulonglong2*)&As[kk * 128 + (r0 ^ swz)];
            ulonglong2 ap1 = *(const ulonglong2*)&As[kk * 128 + (r0 ^ swz) + 4];
            // B: 2 cols, contiguous float2 across warp
            float2 bv = *(const float2*)&Bs[kk * 64 + (c0 ^ swz)];
            ull b0 = pack2(bv.x), b1 = pack2(bv.y);
            ull a2[4] = {ap0.x, ap0.y, ap1.x, ap1.y};
#pragma unroll
            for (int i = 0; i < 4; i++) {
                fma2(acc[i][0], a2[i], b0);
                fma2(acc[i][1], a2[i], b1);
            }
        }

        // write ReLU'd tile: rows (r0+2p, r0+2p+1), cols (c0, c0+1)
#pragma unroll
        for (int p = 0; p < 4; p++) {
            float2 oL, oH;
            oL.x = fmaxf(lo32(acc[p][0]), 0.0f);
            oL.y = fmaxf(lo32(acc[p][1]), 0.0f);
            oH.x = fmaxf(hi32(acc[p][0]), 0.0f);
            oH.y = fmaxf(hi32(acc[p][1]), 0.0f);
            *(float2*)&Ss[(r0 + 2*p)     * 68 + c0] = oL;
            *(float2*)&Ss[(r0 + 2*p + 1) * 68 + c0] = oH;
        }
        __syncthreads();

        // streaming top-9: this thread covers cols [part*16, part*16+16)
#pragma unroll
        for (int t = 0; t < 4; t++) {
            float4 v4 = *(const float4*)&Ss[row * 68 + part * 16 + t * 4];
            int cb = j0 + part * 16 + t * 4;
            float vv[4] = {v4.x, v4.y, v4.z, v4.w};
#pragma unroll
            for (int u = 0; u < 4; u++) {
                float v = vv[u];
                if (v > tv[8]) {
                    tv[8] = v; ti[8] = cb + u;
#pragma unroll
                    for (int q = 8; q > 0; q--) {
                        if (tv[q] > tv[q - 1]) {
                            float tf = tv[q]; tv[q] = tv[q - 1]; tv[q - 1] = tf;
                            int tt = ti[q]; ti[q] = ti[q - 1]; ti[q - 1] = tt;
                        }
                    }
                }
            }
        }
    }
    __syncthreads();

    // merge 4 per-row lists (alias As/Bs region): list id = tid
    float* Mv = sm;                      // 512*9 floats = 4608
    int*   Mi = (int*)(sm + 4608);       // 512*9 ints
#pragma unroll
    for (int q = 0; q < 9; q++) {
        Mv[tid * 9 + q] = tv[q];
        Mi[tid * 9 + q] = ti[q];
    }
    __syncthreads();
    if (tid < 128) {
        int pos0 = 0, pos1 = 0, pos2 = 0, pos3 = 0;
        int obase = (bh * Sq + i0 + tid) * KN;
        for (int kk = 0; kk < KN; kk++) {
            float bv = -2.0f; int bi = 0, bp = 0;
            {
                float v = Mv[(tid * 4 + 0) * 9 + pos0]; int ix = Mi[(tid * 4 + 0) * 9 + pos0];
                if (v > bv || (v == bv && ix < bi)) { bv = v; bi = ix; bp = 0; }
            }
            {
                float v = Mv[(tid * 4 + 1) * 9 + pos1]; int ix = Mi[(tid * 4 + 1) * 9 + pos1];
                if (v > bv || (v == bv && ix < bi)) { bv = v; bi = ix; bp = 1; }
            }
            {
                float v = Mv[(tid * 4 + 2) * 9 + pos2]; int ix = Mi[(tid * 4 + 2) * 9 + pos2];
                if (v > bv || (v == bv && ix < bi)) { bv = v; bi = ix; bp = 2; }
            }
            {
                float v = Mv[(tid * 4 + 3) * 9 + pos3]; int ix = Mi[(tid * 4 + 3) * 9 + pos3];
                if (v > bv || (v == bv && ix < bi)) { bv = v; bi = ix; bp = 3; }
            }
            g_idx[obase + kk] = bi;
            if (bp == 0) pos0++; else if (bp == 1) pos1++; else if (bp == 2) pos2++; else pos3++;
        }
    }
}

// ---------------- prep: transpose conv_w [o][c][kk] -> Wt[kk][c][o] ---------
__global__ void transpose_convw_kernel(const float* __restrict__ w)
{
    int t = blockIdx.x * 256 + threadIdx.x;
    if (t < KN * DKq * DKq) {
        int o = t & 63, c = (t >> 6) & 63, kk = t >> 12;
        g_wt[t] = w[(o * 64 + c) * KN + kk];
    }
}

// ---------------- Kernel D: gather v by idx + grouped conv, scatter to y^T --
// (round-4 version)
__global__ __launch_bounds__(128, 2) void conv_kernel(const float* __restrict__ convb)
{
    extern __shared__ float smd[];
    float* v_s  = smd;                   // [288][64]
    float* w_s  = smd + 288 * 64;        // [64 c][64 o]
    int*   sidx = (int*)(smd + 288 * 64 + 4096);  // [288]

    int bh = blockIdx.y;
    int i0 = blockIdx.x * 32;
    int b  = bh >> 3, h = bh & 7;
    int tid = threadIdx.x;

    for (int t = tid; t < 288; t += 128)
        sidx[t] = g_idx[(bh * Sq + i0 + t / KN) * KN + (t % KN)];

    float4 wreg[8];
#pragma unroll
    for (int p = 0; p < 8; p++)
        wreg[p] = *(const float4*)(g_wt + (tid + 128 * p) * 4);

    __syncthreads();

    const float* vbase = g_v + (size_t)bh * Sq * DKq;
    for (int p = 0; p < 36; p++) {
        int f = tid + 128 * p;
        int r = f >> 4, fq = (f & 15) * 4;
        int j = sidx[r];
        float4 vv = *(const float4*)(vbase + (size_t)j * 64 + fq);
        *(float4*)&v_s[r * 64 + fq] = vv;
    }

    int og = tid & 15; int o0 = og * 4;
    int ig = tid >> 4;
    ull acc[4][2];
#pragma unroll
    for (int t = 0; t < 4; t++) { acc[t][0] = 0ULL; acc[t][1] = 0ULL; }

    for (int kk = 0; kk < KN; kk++) {
        __syncthreads();
#pragma unroll
        for (int p = 0; p < 8; p++)
            *(float4*)&w_s[(tid + 128 * p) * 4] = wreg[p];
        __syncthreads();
        if (kk + 1 < KN) {
#pragma unroll
            for (int p = 0; p < 8; p++)
                wreg[p] = *(const float4*)(g_wt + (kk + 1) * 4096 + (tid + 128 * p) * 4);
        }
#pragma unroll 4
        for (int c = 0; c < 64; c++) {
            ulonglong2 wp = *(const ulonglong2*)&w_s[c * 64 + o0];
#pragma unroll
            for (int t = 0; t < 4; t++) {
                ull v2 = pack2(v_s[(((ig * 4 + t) * KN) + kk) * 64 + c]);
                fma2(acc[t][0], v2, wp.x);
                fma2(acc[t][1], v2, wp.y);
            }
        }
    }

    float4 cb = *(const float4*)(convb + o0);
    int colbase = (h * 64 + (i0 >> 5)) * Mq + b * Sq;
#pragma unroll
    for (int t = 0; t < 4; t++) {
        int il = ig * 4 + t;
        int sp = ((i0 + il) & 31) * 64 + o0;
        float4 o;
        o.x = lo32(acc[t][0]) + cb.x;
        o.y = hi32(acc[t][0]) + cb.y;
        o.z = lo32(acc[t][1]) + cb.z;
        o.w = hi32(acc[t][1]) + cb.w;
        *(float4*)&g_y[colbase + sp] = o;
    }
}

// ---------------- Kernel E: final = y @ Wo^T + b (round-4 version) ----------
__global__ __launch_bounds__(256, 2) void out_gemm_kernel(
    const float* __restrict__ Wo, const float* __restrict__ bo,
    float* __restrict__ outp)
{
    __shared__ __align__(16) float As[16][132];
    __shared__ __align__(16) float Bs[16][132];

    int m0 = blockIdx.y * 128, n0 = blockIdx.x * 128;
    int tid = threadIdx.x, tx = tid & 15, ty = tid >> 4;
    int r0 = ty * 8, c0 = tx * 8;

    ull acc[4][8];
#pragma unroll
    for (int i = 0; i < 4; i++)
#pragma unroll
        for (int j = 0; j < 8; j++) acc[i][j] = 0ULL;

    int lrow = tid >> 2, lk = (tid & 3) * 4;
    int fk = tid >> 5, fm = tid & 31;

    const float* pa0 = g_y + (size_t)fk * Mq + m0 + fm * 4;
    const float* pa1 = g_y + (size_t)(fk + 8) * Mq + m0 + fm * 4;
    const float* pb0 = Wo + (size_t)(n0 + lrow)      * 512 + lk;
    const float* pb1 = Wo + (size_t)(n0 + lrow + 64) * 512 + lk;

    float4 a0 = *(const float4*)(pa0);
    float4 a1 = *(const float4*)(pa1);
    float4 b0 = *(const float4*)(pb0);
    float4 b1 = *(const float4*)(pb1);

    for (int k0 = 0; k0 < 512; k0 += 16) {
        __syncthreads();
        *(float4*)&As[fk][fm * 4]     = a0;
        *(float4*)&As[fk + 8][fm * 4] = a1;
        Bs[lk+0][lrow] = b0.x; Bs[lk+1][lrow] = b0.y; Bs[lk+2][lrow] = b0.z; Bs[lk+3][lrow] = b0.w;
        Bs[lk+0][lrow+64] = b1.x; Bs[lk+1][lrow+64] = b1.y; Bs[lk+2][lrow+64] = b1.z; Bs[lk+3][lrow+64] = b1.w;
        __syncthreads();
        if (k0 + 16 < 512) {
            a0 = *(const float4*)(pa0 + (size_t)(k0 + 16) * Mq);
            a1 = *(const float4*)(pa1 + (size_t)(k0 + 16) * Mq);
            b0 = *(const float4*)(pb0 + k0 + 16);
            b1 = *(const float4*)(pb1 + k0 + 16);
        }
#pragma unroll
        for (int kk = 0; kk < 16; kk++) {
            ulonglong2 ap0 = *(const ulonglong2*)&As[kk][r0];
            ulonglong2 ap1 = *(const ulonglong2*)&As[kk][r0 + 4];
            float4 bv0 = *(const float4*)&Bs[kk][c0];
            float4 bv1 = *(const float4*)&Bs[kk][c0 + 4];
            ull b2[8];
            b2[0] = pack2(bv0.x); b2[1] = pack2(bv0.y); b2[2] = pack2(bv0.z); b2[3] = pack2(bv0.w);
            b2[4] = pack2(bv1.x); b2[5] = pack2(bv1.y); b2[6] = pack2(bv1.z); b2[7] = pack2(bv1.w);
            ull a2[4] = {ap0.x, ap0.y, ap1.x, ap1.y};
#pragma unroll
            for (int i = 0; i < 4; i++)
#pragma unroll
                for (int j = 0; j < 8; j++) fma2(acc[i][j], a2[i], b2[j]);
        }
    }

    float4 bias0 = *(const float4*)(bo + n0 + c0);
    float4 bias1 = *(const float4*)(bo + n0 + c0 + 4);
#pragma unroll
    for (int i = 0; i < 4; i++) {
#pragma unroll
        for (int half = 0; half < 2; half++) {
            int m = m0 + r0 + 2 * i + half;
            float4 o0, o1;
            if (half == 0) {
                o0.x = lo32(acc[i][0]) + bias0.x; o0.y = lo32(acc[i][1]) + bias0.y;
                o0.z = lo32(acc[i][2]) + bias0.z; o0.w = lo32(acc[i][3]) + bias0.w;
                o1.x = lo32(acc[i][4]) + bias1.x; o1.y = lo32(acc[i][5]) + bias1.y;
                o1.z = lo32(acc[i][6]) + bias1.z; o1.w = lo32(acc[i][7]) + bias1.w;
            } else {
                o0.x = hi32(acc[i][0]) + bias0.x; o0.y = hi32(acc[i][1]) + bias0.y;
                o0.z = hi32(acc[i][2]) + bias0.z; o0.w = hi32(acc[i][3]) + bias0.w;
                o1.x = hi32(acc[i][4]) + bias1.x; o1.y = hi32(acc[i][5]) + bias1.y;
                o1.z = hi32(acc[i][6]) + bias1.z; o1.w = hi32(acc[i][7]) + bias1.w;
            }
            float* po = outp + (size_t)m * 512 + n0 + c0;
            *(float4*)po = o0;
            *(float4*)(po + 4) = o1;
        }
    }
}

// ---------------- launch -----------------------------------------------------
extern "C" void kernel_launch(void* const* d_in, const int* in_sizes, int n_in,
                              void* d_out, int out_size)
{
    (void)in_sizes; (void)n_in; (void)out_size;
    const float* x      = (const float*)d_in[0];
    const float* Wq_w   = (const float*)d_in[1];
    const float* Wq_b   = (const float*)d_in[2];
    const float* Wk_w   = (const float*)d_in[3];
    const float* Wk_b   = (const float*)d_in[4];
    const float* Wv_w   = (const float*)d_in[5];
    const float* Wv_b   = (const float*)d_in[6];
    const float* Wo_w   = (const float*)d_in[7];
    const float* Wo_b   = (const float*)d_in[8];
    const float* conv_w = (const float*)d_in[9];
    const float* conv_b = (const float*)d_in[10];
    float* outp = (float*)d_out;

    const int SMEM_C = (8192 + 4096 + 128 * 68) * 4;         // 83968 B
    const int SMEM_D = (288 * 64 + 64 * 64) * 4 + 288 * 4;   // 91264 B
    cudaFuncSetAttribute(sim_topk_kernel, cudaFuncAttributeMaxDynamicSharedMemorySize, SMEM_C);
    cudaFuncSetAttribute(conv_kernel,     cudaFuncAttributeMaxDynamicSharedMemorySize, SMEM_D);

    qkv_gemm_kernel<<<dim3(4, 64, 3), 256>>>(x, Wq_w, Wq_b, Wk_w, Wk_b, Wv_w, Wv_b);
    normalize_kernel<<<16384, 256>>>();
    transpose_convw_kernel<<<144, 256>>>(conv_w);
    sim_topk_kernel<<<dim3(16, 32), 512, SMEM_C>>>();
    conv_kernel<<<dim3(64, 32), 128, SMEM_D>>>(conv_b);
    out_gemm_kernel<<<dim3(4, 64), 256>>>(Wo_w, Wo_b, outp);
}

// round 8
// speedup vs baseline: 1.0142x; 1.0142x over previous
#include <cuda_runtime.h>
#include <math.h>

#define Bq   4
#define Sq   2048
#define Dq   512
#define Hq   8
#define DKq  64
#define KN   9
#define NC   16     /* candidates per row */
#define BHq  32
#define Mq   8192   /* B*S */
#define EPSN 1e-12f

typedef unsigned long long ull;

// ---------------- packed fp32x2 helpers (sm_103a FFMA2) ----------------
__device__ __forceinline__ ull pack2(float x) {
    ull r;
    asm("mov.b64 %0, {%1, %1};" : "=l"(r) : "f"(x));
    return r;
}
__device__ __forceinline__ void fma2(ull& d, ull a, ull b) {
    asm("fma.rn.f32x2 %0, %1, %2, %0;" : "+l"(d) : "l"(a), "l"(b));
}
__device__ __forceinline__ float lo32(ull v) {
    return __uint_as_float((unsigned)v);
}
__device__ __forceinline__ float hi32(ull v) {
    return __uint_as_float((unsigned)(v >> 32));
}
__device__ __forceinline__ float to_tf32(float x) {
    unsigned u;
    asm("cvt.rna.tf32.f32 %0, %1;" : "=r"(u) : "f"(x));
    return __uint_as_float(u);
}

#define MMA_TF32(c, a0, a1, a2, a3, b0, b1)                                \
    asm("mma.sync.aligned.m16n8k8.row.col.f32.tf32.tf32.f32 "              \
        "{%0,%1,%2,%3}, {%4,%5,%6,%7}, {%8,%9}, {%0,%1,%2,%3};"            \
        : "+f"(c[0]), "+f"(c[1]), "+f"(c[2]), "+f"(c[3])                   \
        : "r"(a0), "r"(a1), "r"(a2), "r"(a3), "r"(b0), "r"(b1))

// ---------------- scratch (device globals; no allocation) ----------------
__device__ float g_q[BHq * Sq * DKq];      // normalized q (fp32)
__device__ float g_k[BHq * Sq * DKq];      // normalized k (fp32)
__device__ float g_v[BHq * Sq * DKq];
__device__ float g_kh[BHq * Sq * DKq];     // normalized k, tf32
__device__ float g_qh[BHq * Sq * DKq];     // normalized q, tf32
__device__ int   g_idx[BHq * Sq * KN];     // top-9 indices, sorted desc by sim
__device__ float g_y[Dq * Mq];             // y^T: [col][b*S + s']
__device__ float g_wt[KN * DKq * DKq];     // Wt[kk][c][o]

// ---------------- Kernel A: QKV GEMM  out = x @ W^T + b, split-head layout ----
__global__ __launch_bounds__(256, 2) void qkv_gemm_kernel(
    const float* __restrict__ x,
    const float* __restrict__ Wq, const float* __restrict__ bq,
    const float* __restrict__ Wk, const float* __restrict__ bk,
    const float* __restrict__ Wv, const float* __restrict__ bv)
{
    __shared__ __align__(16) float As[16][132];
    __shared__ __align__(16) float Bs[16][132];

    const float* W; const float* bias; float* out;
    int z = blockIdx.z;
    if (z == 0)      { W = Wq; bias = bq; out = g_q; }
    else if (z == 1) { W = Wk; bias = bk; out = g_k; }
    else             { W = Wv; bias = bv; out = g_v; }

    int m0 = blockIdx.y * 128;
    int n0 = blockIdx.x * 128;
    int tid = threadIdx.x;
    int tx = tid & 15, ty = tid >> 4;
    int r0 = ty * 8, c0 = tx * 8;

    ull acc[4][8];
#pragma unroll
    for (int i = 0; i < 4; i++)
#pragma unroll
        for (int j = 0; j < 8; j++) acc[i][j] = 0ULL;

    int lrow = tid >> 2;
    int lk   = (tid & 3) * 4;

    const float* pa0 = x + (size_t)(m0 + lrow)      * 512 + lk;
    const float* pa1 = x + (size_t)(m0 + lrow + 64) * 512 + lk;
    const float* pb0 = W + (size_t)(n0 + lrow)      * 512 + lk;
    const float* pb1 = W + (size_t)(n0 + lrow + 64) * 512 + lk;

    float4 a0 = *(const float4*)(pa0);
    float4 a1 = *(const float4*)(pa1);
    float4 b0 = *(const float4*)(pb0);
    float4 b1 = *(const float4*)(pb1);

    for (int k0 = 0; k0 < 512; k0 += 16) {
        __syncthreads();
        As[lk+0][lrow] = a0.x; As[lk+1][lrow] = a0.y; As[lk+2][lrow] = a0.z; As[lk+3][lrow] = a0.w;
        As[lk+0][lrow+64] = a1.x; As[lk+1][lrow+64] = a1.y; As[lk+2][lrow+64] = a1.z; As[lk+3][lrow+64] = a1.w;
        Bs[lk+0][lrow] = b0.x; Bs[lk+1][lrow] = b0.y; Bs[lk+2][lrow] = b0.z; Bs[lk+3][lrow] = b0.w;
        Bs[lk+0][lrow+64] = b1.x; Bs[lk+1][lrow+64] = b1.y; Bs[lk+2][lrow+64] = b1.z; Bs[lk+3][lrow+64] = b1.w;
        __syncthreads();
        if (k0 + 16 < 512) {
            a0 = *(const float4*)(pa0 + k0 + 16);
            a1 = *(const float4*)(pa1 + k0 + 16);
            b0 = *(const float4*)(pb0 + k0 + 16);
            b1 = *(const float4*)(pb1 + k0 + 16);
        }
#pragma unroll
        for (int kk = 0; kk < 16; kk++) {
            ulonglong2 ap0 = *(const ulonglong2*)&As[kk][r0];
            ulonglong2 ap1 = *(const ulonglong2*)&As[kk][r0 + 4];
            float4 bv0 = *(const float4*)&Bs[kk][c0];
            float4 bv1 = *(const float4*)&Bs[kk][c0 + 4];
            ull b2[8];
            b2[0] = pack2(bv0.x); b2[1] = pack2(bv0.y); b2[2] = pack2(bv0.z); b2[3] = pack2(bv0.w);
            b2[4] = pack2(bv1.x); b2[5] = pack2(bv1.y); b2[6] = pack2(bv1.z); b2[7] = pack2(bv1.w);
            ull a2[4] = {ap0.x, ap0.y, ap1.x, ap1.y};
#pragma unroll
            for (int i = 0; i < 4; i++)
#pragma unroll
                for (int j = 0; j < 8; j++) fma2(acc[i][j], a2[i], b2[j]);
        }
    }

    float4 bias0 = *(const float4*)(bias + n0 + c0);
    float4 bias1 = *(const float4*)(bias + n0 + c0 + 4);
    int n = n0 + c0;
    int h = n >> 6, c = n & 63;
#pragma unroll
    for (int i = 0; i < 4; i++) {
#pragma unroll
        for (int half = 0; half < 2; half++) {
            int m = m0 + r0 + 2 * i + half;
            int bb = m >> 11;
            int s  = m & 2047;
            float4 o0, o1;
            if (half == 0) {
                o0.x = lo32(acc[i][0]) + bias0.x; o0.y = lo32(acc[i][1]) + bias0.y;
                o0.z = lo32(acc[i][2]) + bias0.z; o0.w = lo32(acc[i][3]) + bias0.w;
                o1.x = lo32(acc[i][4]) + bias1.x; o1.y = lo32(acc[i][5]) + bias1.y;
                o1.z = lo32(acc[i][6]) + bias1.z; o1.w = lo32(acc[i][7]) + bias1.w;
            } else {
                o0.x = hi32(acc[i][0]) + bias0.x; o0.y = hi32(acc[i][1]) + bias0.y;
                o0.z = hi32(acc[i][2]) + bias0.z; o0.w = hi32(acc[i][3]) + bias0.w;
                o1.x = hi32(acc[i][4]) + bias1.x; o1.y = hi32(acc[i][5]) + bias1.y;
                o1.z = hi32(acc[i][6]) + bias1.z; o1.w = hi32(acc[i][7]) + bias1.w;
            }
            float* po = out + ((size_t)(bb * Hq + h) * Sq + s) * DKq + c;
            *(float4*)po = o0;
            *(float4*)(po + 4) = o1;
        }
    }
}

// ---------------- Kernel B: L2-normalize q,k (in place) + tf32 copy ---------
__global__ __launch_bounds__(256) void normalize_split_kernel()
{
    int gw   = blockIdx.x * 8 + (threadIdx.x >> 5);
    int lane = threadIdx.x & 31;
    float* p; float* ph;
    if (gw < BHq * Sq) {
        p  = g_k  + (size_t)gw * 64;
        ph = g_kh + (size_t)gw * 64;
    } else {
        int r = gw - BHq * Sq;
        p  = g_q  + (size_t)r * 64;
        ph = g_qh + (size_t)r * 64;
    }
    float v0 = p[lane], v1 = p[lane + 32];
    float ss = v0 * v0 + v1 * v1;
#pragma unroll
    for (int o = 16; o; o >>= 1) ss += __shfl_xor_sync(0xffffffffu, ss, o);
    float inv = 1.0f / fmaxf(sqrtf(ss), EPSN);
    float x0 = v0 * inv, x1 = v1 * inv;
    p[lane]       = x0;
    p[lane + 32]  = x1;
    ph[lane]      = to_tf32(x0);
    ph[lane + 32] = to_tf32(x1);
}

// ---------------- Kernel C: tf32 mma pruning (top-16) + exact fp32 rescore --
// grid (S/64, BH); 256 threads; 2 blocks/SM. Tile 64x64, k=64.
__global__ __launch_bounds__(256, 2) void sim_topk_kernel()
{
    extern __shared__ __align__(16) float sm[];
    float* As = sm;            // [64][68] kn tf32
    float* Bs = sm + 4352;     // [64][68] qn tf32
    float* Ss = sm + 8704;     // [64][68] sim tile; later kn fp32 tile

    int bh = blockIdx.y;
    int i0 = blockIdx.x * 64;
    int tid = threadIdx.x;
    int lane = tid & 31;
    int wid = tid >> 5;
    int g = lane >> 2, t4 = lane & 3;
    int wr = (wid & 3) * 16;
    int jbase = (wid >> 2) * 32;

    const float* khb = g_kh + (size_t)bh * Sq * DKq;
    const float* qhb = g_qh + (size_t)bh * Sq * DKq;

    // fill As (row-major, stride 68), once
#pragma unroll
    for (int p = 0; p < 4; p++) {
        int f = tid + 256 * p;
        int r = f >> 4, dq = (f & 15) * 4;
        *(float4*)&As[r * 68 + dq] = *(const float4*)(khb + (size_t)(i0 + r) * 64 + dq);
    }

    float tv[NC]; int ti[NC];
#pragma unroll
    for (int q = 0; q < NC; q++) { tv[q] = -1.0f; ti[q] = 0; }

    int row = tid >> 2, part = tid & 3;   // topk: 4 threads/row, 16 cols each

    // prefetch first B tile
    float4 brh[4];
#pragma unroll
    for (int p = 0; p < 4; p++) {
        int f = tid + 256 * p;
        int r = f >> 4, dq = (f & 15) * 4;
        brh[p] = *(const float4*)(qhb + (size_t)r * 64 + dq);
    }

    const unsigned* Ah = (const unsigned*)As;
    const unsigned* Bh = (const unsigned*)Bs;

    for (int j0 = 0; j0 < Sq; j0 += 64) {
        __syncthreads();
#pragma unroll
        for (int p = 0; p < 4; p++) {
            int f = tid + 256 * p;
            int r = f >> 4, dq = (f & 15) * 4;
            *(float4*)&Bs[r * 68 + dq] = brh[p];
        }
        __syncthreads();
        if (j0 + 64 < Sq) {
#pragma unroll
            for (int p = 0; p < 4; p++) {
                int f = tid + 256 * p;
                int r = f >> 4, dq = (f & 15) * 4;
                brh[p] = *(const float4*)(qhb + (size_t)(j0 + 64 + r) * 64 + dq);
            }
        }

        float c[4][4];
#pragma unroll
        for (int jc = 0; jc < 4; jc++)
#pragma unroll
            for (int u = 0; u < 4; u++) c[jc][u] = 0.0f;

#pragma unroll
        for (int kc = 0; kc < 8; kc++) {
            int ao = (wr + g) * 68 + kc * 8 + t4;
            unsigned ah0 = Ah[ao], ah1 = Ah[ao + 544], ah2 = Ah[ao + 4], ah3 = Ah[ao + 548];
#pragma unroll
            for (int jc = 0; jc < 4; jc++) {
                int bo = (jbase + jc * 8 + g) * 68 + kc * 8 + t4;
                unsigned bh0 = Bh[bo], bh1 = Bh[bo + 4];
                MMA_TF32(c[jc], ah0, ah1, ah2, ah3, bh0, bh1);
            }
        }

        // write ReLU'd tile to Ss
#pragma unroll
        for (int jc = 0; jc < 4; jc++) {
            int col = jbase + jc * 8 + 2 * t4;
            int rr  = wr + g;
            float2 s0, s1;
            s0.x = fmaxf(c[jc][0], 0.0f); s0.y = fmaxf(c[jc][1], 0.0f);
            s1.x = fmaxf(c[jc][2], 0.0f); s1.y = fmaxf(c[jc][3], 0.0f);
            *(float2*)&Ss[rr * 68 + col]       = s0;
            *(float2*)&Ss[(rr + 8) * 68 + col] = s1;
        }
        __syncthreads();

        // streaming top-16 (approx): this thread covers cols [part*16, +16)
#pragma unroll
        for (int t = 0; t < 4; t++) {
            float4 v4 = *(const float4*)&Ss[row * 68 + part * 16 + t * 4];
            int cb = j0 + part * 16 + t * 4;
            float vv[4] = {v4.x, v4.y, v4.z, v4.w};
#pragma unroll
            for (int u = 0; u < 4; u++) {
                float v = vv[u];
                if (v > tv[NC - 1]) {
                    tv[NC - 1] = v; ti[NC - 1] = cb + u;
#pragma unroll
                    for (int q = NC - 1; q > 0; q--) {
                        if (tv[q] > tv[q - 1]) {
                            float tf = tv[q]; tv[q] = tv[q - 1]; tv[q - 1] = tf;
                            int tt = ti[q]; ti[q] = ti[q - 1]; ti[q - 1] = tt;
                        }
                    }
                }
            }
        }
    }
    __syncthreads();

    // dump per-thread candidate lists (alias As/Bs region)
    float* Mv = sm;                      // 256*16 floats = 4096
    int*   Mi = (int*)(sm + 4096);       // 256*16 ints
#pragma unroll
    for (int q = 0; q < NC; q++) {
        Mv[tid * NC + q] = tv[q];
        Mi[tid * NC + q] = ti[q];
    }
    // stage exact fp32 kn tile into Ss region (safe: Ss reads done)
#pragma unroll
    for (int p = 0; p < 4; p++) {
        int f = tid + 256 * p;
        int r = f >> 4, dq = (f & 15) * 4;
        *(float4*)&Ss[r * 68 + dq] =
            *(const float4*)(g_k + ((size_t)bh * Sq + i0 + r) * 64 + dq);
    }
    __syncthreads();

    if (tid < 64) {
        // merge 4 sorted approx lists -> 16 candidates
        int pos0 = 0, pos1 = 0, pos2 = 0, pos3 = 0;
        int cand[NC];
        for (int kk = 0; kk < NC; kk++) {
            float bv = -2.0f; int bi = 0x7fffffff, bp = 0;
            {
                float v = Mv[(tid * 4 + 0) * NC + pos0]; int ix = Mi[(tid * 4 + 0) * NC + pos0];
                if (v > bv || (v == bv && ix < bi)) { bv = v; bi = ix; bp = 0; }
            }
            {
                float v = Mv[(tid * 4 + 1) * NC + pos1]; int ix = Mi[(tid * 4 + 1) * NC + pos1];
                if (v > bv || (v == bv && ix < bi)) { bv = v; bi = ix; bp = 1; }
            }
            {
                float v = Mv[(tid * 4 + 2) * NC + pos2]; int ix = Mi[(tid * 4 + 2) * NC + pos2];
                if (v > bv || (v == bv && ix < bi)) { bv = v; bi = ix; bp = 2; }
            }
            {
                float v = Mv[(tid * 4 + 3) * NC + pos3]; int ix = Mi[(tid * 4 + 3) * NC + pos3];
                if (v > bv || (v == bv && ix < bi)) { bv = v; bi = ix; bp = 3; }
            }
            cand[kk] = bi;
            if (bp == 0) pos0++; else if (bp == 1) pos1++; else if (bp == 2) pos2++; else pos3++;
        }

        // exact fp32 rescore of the 16 candidates
        const float* kr = &Ss[tid * 68];
        float vals[NC];
#pragma unroll 1
        for (int c2 = 0; c2 < NC; c2++) {
            int j = cand[c2];
            const float* qrow = g_q + ((size_t)bh * Sq + j) * 64;
            float s = 0.0f;
#pragma unroll
            for (int d = 0; d < 64; d += 4) {
                float4 qv = *(const float4*)(qrow + d);
                s = fmaf(kr[d + 0], qv.x, s);
                s = fmaf(kr[d + 1], qv.y, s);
                s = fmaf(kr[d + 2], qv.z, s);
                s = fmaf(kr[d + 3], qv.w, s);
            }
            vals[c2] = fmaxf(s, 0.0f);
        }

        // partial selection sort: top-9 by (value desc, index asc)
        int obase = (bh * Sq + i0 + tid) * KN;
        for (int a = 0; a < KN; a++) {
            int best = a;
            for (int c2 = a + 1; c2 < NC; c2++) {
                if (vals[c2] > vals[best] ||
                    (vals[c2] == vals[best] && cand[c2] < cand[best]))
                    best = c2;
            }
            float tvv = vals[a]; vals[a] = vals[best]; vals[best] = tvv;
            int   tii = cand[a]; cand[a] = cand[best]; cand[best] = tii;
            g_idx[obase + a] = cand[a];
        }
    }
}

// ---------------- prep: transpose conv_w [o][c][kk] -> Wt[kk][c][o] ---------
__global__ void transpose_convw_kernel(const float* __restrict__ w)
{
    int t = blockIdx.x * 256 + threadIdx.x;
    if (t < KN * DKq * DKq) {
        int o = t & 63, c = (t >> 6) & 63, kk = t >> 12;
        g_wt[t] = w[(o * 64 + c) * KN + kk];
    }
}

// ---------------- Kernel D: gather v by idx + grouped conv, scatter to y^T --
__global__ __launch_bounds__(128, 2) void conv_kernel(const float* __restrict__ convb)
{
    extern __shared__ float smd[];
    float* v_s  = smd;                   // [288][64]
    float* w_s  = smd + 288 * 64;        // [64 c][64 o]
    int*   sidx = (int*)(smd + 288 * 64 + 4096);  // [288]

    int bh = blockIdx.y;
    int i0 = blockIdx.x * 32;
    int b  = bh >> 3, h = bh & 7;
    int tid = threadIdx.x;

    for (int t = tid; t < 288; t += 128)
        sidx[t] = g_idx[(bh * Sq + i0 + t / KN) * KN + (t % KN)];

    float4 wreg[8];
#pragma unroll
    for (int p = 0; p < 8; p++)
        wreg[p] = *(const float4*)(g_wt + (tid + 128 * p) * 4);

    __syncthreads();

    const float* vbase = g_v + (size_t)bh * Sq * DKq;
    for (int p = 0; p < 36; p++) {
        int f = tid + 128 * p;
        int r = f >> 4, fq = (f & 15) * 4;
        int j = sidx[r];
        float4 vv = *(const float4*)(vbase + (size_t)j * 64 + fq);
        *(float4*)&v_s[r * 64 + fq] = vv;
    }

    int og = tid & 15; int o0 = og * 4;
    int ig = tid >> 4;
    ull acc[4][2];
#pragma unroll
    for (int t = 0; t < 4; t++) { acc[t][0] = 0ULL; acc[t][1] = 0ULL; }

    for (int kk = 0; kk < KN; kk++) {
        __syncthreads();
#pragma unroll
        for (int p = 0; p < 8; p++)
            *(float4*)&w_s[(tid + 128 * p) * 4] = wreg[p];
        __syncthreads();
        if (kk + 1 < KN) {
#pragma unroll
            for (int p = 0; p < 8; p++)
                wreg[p] = *(const float4*)(g_wt + (kk + 1) * 4096 + (tid + 128 * p) * 4);
        }
#pragma unroll 4
        for (int c = 0; c < 64; c++) {
            ulonglong2 wp = *(const ulonglong2*)&w_s[c * 64 + o0];
#pragma unroll
            for (int t = 0; t < 4; t++) {
                ull v2 = pack2(v_s[(((ig * 4 + t) * KN) + kk) * 64 + c]);
                fma2(acc[t][0], v2, wp.x);
                fma2(acc[t][1], v2, wp.y);
            }
        }
    }

    float4 cb = *(const float4*)(convb + o0);
    int colbase = (h * 64 + (i0 >> 5)) * Mq + b * Sq;
#pragma unroll
    for (int t = 0; t < 4; t++) {
        int il = ig * 4 + t;
        int sp = ((i0 + il) & 31) * 64 + o0;
        float4 o;
        o.x = lo32(acc[t][0]) + cb.x;
        o.y = hi32(acc[t][0]) + cb.y;
        o.z = lo32(acc[t][1]) + cb.z;
        o.w = hi32(acc[t][1]) + cb.w;
        *(float4*)&g_y[colbase + sp] = o;
    }
}

// ---------------- Kernel E: final = y @ Wo^T + b ----------------------------
__global__ __launch_bounds__(256, 2) void out_gemm_kernel(
    const float* __restrict__ Wo, const float* __restrict__ bo,
    float* __restrict__ outp)
{
    __shared__ __align__(16) float As[16][132];
    __shared__ __align__(16) float Bs[16][132];

    int m0 = blockIdx.y * 128, n0 = blockIdx.x * 128;
    int tid = threadIdx.x, tx = tid & 15, ty = tid >> 4;
    int r0 = ty * 8, c0 = tx * 8;

    ull acc[4][8];
#pragma unroll
    for (int i = 0; i < 4; i++)
#pragma unroll
        for (int j = 0; j < 8; j++) acc[i][j] = 0ULL;

    int lrow = tid >> 2, lk = (tid & 3) * 4;
    int fk = tid >> 5, fm = tid & 31;

    const float* pa0 = g_y + (size_t)fk * Mq + m0 + fm * 4;
    const float* pa1 = g_y + (size_t)(fk + 8) * Mq + m0 + fm * 4;
    const float* pb0 = Wo + (size_t)(n0 + lrow)      * 512 + lk;
    const float* pb1 = Wo + (size_t)(n0 + lrow + 64) * 512 + lk;

    float4 a0 = *(const float4*)(pa0);
    float4 a1 = *(const float4*)(pa1);
    float4 b0 = *(const float4*)(pb0);
    float4 b1 = *(const float4*)(pb1);

    for (int k0 = 0; k0 < 512; k0 += 16) {
        __syncthreads();
        *(float4*)&As[fk][fm * 4]     = a0;
        *(float4*)&As[fk + 8][fm * 4] = a1;
        Bs[lk+0][lrow] = b0.x; Bs[lk+1][lrow] = b0.y; Bs[lk+2][lrow] = b0.z; Bs[lk+3][lrow] = b0.w;
        Bs[lk+0][lrow+64] = b1.x; Bs[lk+1][lrow+64] = b1.y; Bs[lk+2][lrow+64] = b1.z; Bs[lk+3][lrow+64] = b1.w;
        __syncthreads();
        if (k0 + 16 < 512) {
            a0 = *(const float4*)(pa0 + (size_t)(k0 + 16) * Mq);
            a1 = *(const float4*)(pa1 + (size_t)(k0 + 16) * Mq);
            b0 = *(const float4*)(pb0 + k0 + 16);
            b1 = *(const float4*)(pb1 + k0 + 16);
        }
#pragma unroll
        for (int kk = 0; kk < 16; kk++) {
            ulonglong2 ap0 = *(const ulonglong2*)&As[kk][r0];
            ulonglong2 ap1 = *(const ulonglong2*)&As[kk][r0 + 4];
            float4 bv0 = *(const float4*)&Bs[kk][c0];
            float4 bv1 = *(const float4*)&Bs[kk][c0 + 4];
            ull b2[8];
            b2[0] = pack2(bv0.x); b2[1] = pack2(bv0.y); b2[2] = pack2(bv0.z); b2[3] = pack2(bv0.w);
            b2[4] = pack2(bv1.x); b2[5] = pack2(bv1.y); b2[6] = pack2(bv1.z); b2[7] = pack2(bv1.w);
            ull a2[4] = {ap0.x, ap0.y, ap1.x, ap1.y};
#pragma unroll
            for (int i = 0; i < 4; i++)
#pragma unroll
                for (int j = 0; j < 8; j++) fma2(acc[i][j], a2[i], b2[j]);
        }
    }

    float4 bias0 = *(const float4*)(bo + n0 + c0);
    float4 bias1 = *(const float4*)(bo + n0 + c0 + 4);
#pragma unroll
    for (int i = 0; i < 4; i++) {
#pragma unroll
        for (int half = 0; half < 2; half++) {
            int m = m0 + r0 + 2 * i + half;
            float4 o0, o1;
            if (half == 0) {
                o0.x = lo32(acc[i][0]) + bias0.x; o0.y = lo32(acc[i][1]) + bias0.y;
                o0.z = lo32(acc[i][2]) + bias0.z; o0.w = lo32(acc[i][3]) + bias0.w;
                o1.x = lo32(acc[i][4]) + bias1.x; o1.y = lo32(acc[i][5]) + bias1.y;
                o1.z = lo32(acc[i][6]) + bias1.z; o1.w = lo32(acc[i][7]) + bias1.w;
            } else {
                o0.x = hi32(acc[i][0]) + bias0.x; o0.y = hi32(acc[i][1]) + bias0.y;
                o0.z = hi32(acc[i][2]) + bias0.z; o0.w = hi32(acc[i][3]) + bias0.w;
                o1.x = hi32(acc[i][4]) + bias1.x; o1.y = hi32(acc[i][5]) + bias1.y;
                o1.z = hi32(acc[i][6]) + bias1.z; o1.w = hi32(acc[i][7]) + bias1.w;
            }
            float* po = outp + (size_t)m * 512 + n0 + c0;
            *(float4*)po = o0;
            *(float4*)(po + 4) = o1;
        }
    }
}

// ---------------- launch -----------------------------------------------------
extern "C" void kernel_launch(void* const* d_in, const int* in_sizes, int n_in,
                              void* d_out, int out_size)
{
    (void)in_sizes; (void)n_in; (void)out_size;
    const float* x      = (const float*)d_in[0];
    const float* Wq_w   = (const float*)d_in[1];
    const float* Wq_b   = (const float*)d_in[2];
    const float* Wk_w   = (const float*)d_in[3];
    const float* Wk_b   = (const float*)d_in[4];
    const float* Wv_w   = (const float*)d_in[5];
    const float* Wv_b   = (const float*)d_in[6];
    const float* Wo_w   = (const float*)d_in[7];
    const float* Wo_b   = (const float*)d_in[8];
    const float* conv_w = (const float*)d_in[9];
    const float* conv_b = (const float*)d_in[10];
    float* outp = (float*)d_out;

    const int SMEM_C = 13056 * 4;                            // 52224 B
    const int SMEM_D = (288 * 64 + 64 * 64) * 4 + 288 * 4;   // 91264 B
    cudaFuncSetAttribute(sim_topk_kernel, cudaFuncAttributeMaxDynamicSharedMemorySize, SMEM_C);
    cudaFuncSetAttribute(conv_kernel,     cudaFuncAttributeMaxDynamicSharedMemorySize, SMEM_D);

    qkv_gemm_kernel<<<dim3(4, 64, 3), 256>>>(x, Wq_w, Wq_b, Wk_w, Wk_b, Wv_w, Wv_b);
    normalize_split_kernel<<<16384, 256>>>();
    transpose_convw_kernel<<<144, 256>>>(conv_w);
    sim_topk_kernel<<<dim3(32, 32), 256, SMEM_C>>>();
    conv_kernel<<<dim3(64, 32), 128, SMEM_D>>>(conv_b);
    out_gemm_kernel<<<dim3(4, 64), 256>>>(Wo_w, Wo_b, outp);
}

// round 9
// speedup vs baseline: 1.2618x; 1.2442x over previous
#include <cuda_runtime.h>
#include <math.h>

#define Bq   4
#define Sq   2048
#define Dq   512
#define Hq   8
#define DKq  64
#define KN   9
#define NC   12     /* candidates per row */
#define BHq  32
#define Mq   8192   /* B*S */
#define EPSN 1e-12f

typedef unsigned long long ull;

// ---------------- packed fp32x2 helpers (sm_103a FFMA2) ----------------
__device__ __forceinline__ ull pack2(float x) {
    ull r;
    asm("mov.b64 %0, {%1, %1};" : "=l"(r) : "f"(x));
    return r;
}
__device__ __forceinline__ void fma2(ull& d, ull a, ull b) {
    asm("fma.rn.f32x2 %0, %1, %2, %0;" : "+l"(d) : "l"(a), "l"(b));
}
__device__ __forceinline__ float lo32(ull v) {
    return __uint_as_float((unsigned)v);
}
__device__ __forceinline__ float hi32(ull v) {
    return __uint_as_float((unsigned)(v >> 32));
}
__device__ __forceinline__ float to_tf32(float x) {
    unsigned u;
    asm("cvt.rna.tf32.f32 %0, %1;" : "=r"(u) : "f"(x));
    return __uint_as_float(u);
}

#define MMA_TF32(c, a0, a1, a2, a3, b0, b1)                                \
    asm("mma.sync.aligned.m16n8k8.row.col.f32.tf32.tf32.f32 "              \
        "{%0,%1,%2,%3}, {%4,%5,%6,%7}, {%8,%9}, {%0,%1,%2,%3};"            \
        : "+f"(c[0]), "+f"(c[1]), "+f"(c[2]), "+f"(c[3])                   \
        : "r"(a0), "r"(a1), "r"(a2), "r"(a3), "r"(b0), "r"(b1))

// ---------------- scratch (device globals; no allocation) ----------------
__device__ float g_q[BHq * Sq * DKq];      // normalized q (fp32)
__device__ float g_k[BHq * Sq * DKq];      // normalized k (fp32)
__device__ float g_v[BHq * Sq * DKq];
__device__ float g_kh[BHq * Sq * DKq];     // normalized k, tf32
__device__ float g_qh[BHq * Sq * DKq];     // normalized q, tf32
__device__ int   g_idx[BHq * Sq * KN];     // top-9 indices, sorted desc by sim
__device__ float g_y[Dq * Mq];             // y^T: [col][b*S + s']
__device__ float g_wt[KN * DKq * DKq];     // Wt[kk][c][o]

// ---------------- Kernel A: QKV GEMM  out = x @ W^T + b, split-head layout ----
__global__ __launch_bounds__(256, 2) void qkv_gemm_kernel(
    const float* __restrict__ x,
    const float* __restrict__ Wq, const float* __restrict__ bq,
    const float* __restrict__ Wk, const float* __restrict__ bk,
    const float* __restrict__ Wv, const float* __restrict__ bv)
{
    __shared__ __align__(16) float As[16][132];
    __shared__ __align__(16) float Bs[16][132];

    const float* W; const float* bias; float* out;
    int z = blockIdx.z;
    if (z == 0)      { W = Wq; bias = bq; out = g_q; }
    else if (z == 1) { W = Wk; bias = bk; out = g_k; }
    else             { W = Wv; bias = bv; out = g_v; }

    int m0 = blockIdx.y * 128;
    int n0 = blockIdx.x * 128;
    int tid = threadIdx.x;
    int tx = tid & 15, ty = tid >> 4;
    int r0 = ty * 8, c0 = tx * 8;

    ull acc[4][8];
#pragma unroll
    for (int i = 0; i < 4; i++)
#pragma unroll
        for (int j = 0; j < 8; j++) acc[i][j] = 0ULL;

    int lrow = tid >> 2;
    int lk   = (tid & 3) * 4;

    const float* pa0 = x + (size_t)(m0 + lrow)      * 512 + lk;
    const float* pa1 = x + (size_t)(m0 + lrow + 64) * 512 + lk;
    const float* pb0 = W + (size_t)(n0 + lrow)      * 512 + lk;
    const float* pb1 = W + (size_t)(n0 + lrow + 64) * 512 + lk;

    float4 a0 = *(const float4*)(pa0);
    float4 a1 = *(const float4*)(pa1);
    float4 b0 = *(const float4*)(pb0);
    float4 b1 = *(const float4*)(pb1);

    for (int k0 = 0; k0 < 512; k0 += 16) {
        __syncthreads();
        As[lk+0][lrow] = a0.x; As[lk+1][lrow] = a0.y; As[lk+2][lrow] = a0.z; As[lk+3][lrow] = a0.w;
        As[lk+0][lrow+64] = a1.x; As[lk+1][lrow+64] = a1.y; As[lk+2][lrow+64] = a1.z; As[lk+3][lrow+64] = a1.w;
        Bs[lk+0][lrow] = b0.x; Bs[lk+1][lrow] = b0.y; Bs[lk+2][lrow] = b0.z; Bs[lk+3][lrow] = b0.w;
        Bs[lk+0][lrow+64] = b1.x; Bs[lk+1][lrow+64] = b1.y; Bs[lk+2][lrow+64] = b1.z; Bs[lk+3][lrow+64] = b1.w;
        __syncthreads();
        if (k0 + 16 < 512) {
            a0 = *(const float4*)(pa0 + k0 + 16);
            a1 = *(const float4*)(pa1 + k0 + 16);
            b0 = *(const float4*)(pb0 + k0 + 16);
            b1 = *(const float4*)(pb1 + k0 + 16);
        }
#pragma unroll
        for (int kk = 0; kk < 16; kk++) {
            ulonglong2 ap0 = *(const ulonglong2*)&As[kk][r0];
            ulonglong2 ap1 = *(const ulonglong2*)&As[kk][r0 + 4];
            float4 bv0 = *(const float4*)&Bs[kk][c0];
            float4 bv1 = *(const float4*)&Bs[kk][c0 + 4];
            ull b2[8];
            b2[0] = pack2(bv0.x); b2[1] = pack2(bv0.y); b2[2] = pack2(bv0.z); b2[3] = pack2(bv0.w);
            b2[4] = pack2(bv1.x); b2[5] = pack2(bv1.y); b2[6] = pack2(bv1.z); b2[7] = pack2(bv1.w);
            ull a2[4] = {ap0.x, ap0.y, ap1.x, ap1.y};
#pragma unroll
            for (int i = 0; i < 4; i++)
#pragma unroll
                for (int j = 0; j < 8; j++) fma2(acc[i][j], a2[i], b2[j]);
        }
    }

    float4 bias0 = *(const float4*)(bias + n0 + c0);
    float4 bias1 = *(const float4*)(bias + n0 + c0 + 4);
    int n = n0 + c0;
    int h = n >> 6, c = n & 63;
#pragma unroll
    for (int i = 0; i < 4; i++) {
#pragma unroll
        for (int half = 0; half < 2; half++) {
            int m = m0 + r0 + 2 * i + half;
            int bb = m >> 11;
            int s  = m & 2047;
            float4 o0, o1;
            if (half == 0) {
                o0.x = lo32(acc[i][0]) + bias0.x; o0.y = lo32(acc[i][1]) + bias0.y;
                o0.z = lo32(acc[i][2]) + bias0.z; o0.w = lo32(acc[i][3]) + bias0.w;
                o1.x = lo32(acc[i][4]) + bias1.x; o1.y = lo32(acc[i][5]) + bias1.y;
                o1.z = lo32(acc[i][6]) + bias1.z; o1.w = lo32(acc[i][7]) + bias1.w;
            } else {
                o0.x = hi32(acc[i][0]) + bias0.x; o0.y = hi32(acc[i][1]) + bias0.y;
                o0.z = hi32(acc[i][2]) + bias0.z; o0.w = hi32(acc[i][3]) + bias0.w;
                o1.x = hi32(acc[i][4]) + bias1.x; o1.y = hi32(acc[i][5]) + bias1.y;
                o1.z = hi32(acc[i][6]) + bias1.z; o1.w = hi32(acc[i][7]) + bias1.w;
            }
            float* po = out + ((size_t)(bb * Hq + h) * Sq + s) * DKq + c;
            *(float4*)po = o0;
            *(float4*)(po + 4) = o1;
        }
    }
}

// ---------------- Kernel B: L2-normalize q,k (in place) + tf32 copy ---------
__global__ __launch_bounds__(256) void normalize_split_kernel()
{
    int gw   = blockIdx.x * 8 + (threadIdx.x >> 5);
    int lane = threadIdx.x & 31;
    float* p; float* ph;
    if (gw < BHq * Sq) {
        p  = g_k  + (size_t)gw * 64;
        ph = g_kh + (size_t)gw * 64;
    } else {
        int r = gw - BHq * Sq;
        p  = g_q  + (size_t)r * 64;
        ph = g_qh + (size_t)r * 64;
    }
    float v0 = p[lane], v1 = p[lane + 32];
    float ss = v0 * v0 + v1 * v1;
#pragma unroll
    for (int o = 16; o; o >>= 1) ss += __shfl_xor_sync(0xffffffffu, ss, o);
    float inv = 1.0f / fmaxf(sqrtf(ss), EPSN);
    float x0 = v0 * inv, x1 = v1 * inv;
    p[lane]       = x0;
    p[lane + 32]  = x1;
    ph[lane]      = to_tf32(x0);
    ph[lane + 32] = to_tf32(x1);
}

// ---------------- Kernel C: tf32 mma pruning (top-12) + exact fp32 rescore --
// grid (S/64, BH); 256 threads; 3 blocks/SM. Tile 64x64, k=64.
__global__ __launch_bounds__(256, 3) void sim_topk_kernel()
{
    extern __shared__ __align__(16) float sm[];
    float* As = sm;            // [64][68] kn tf32
    float* Bs = sm + 4352;     // [64][68] qn tf32
    float* Ss = sm + 8704;     // [64][68] sim tile; later kn fp32 tile

    int bh = blockIdx.y;
    int i0 = blockIdx.x * 64;
    int tid = threadIdx.x;
    int lane = tid & 31;
    int wid = tid >> 5;
    int g = lane >> 2, t4 = lane & 3;
    int wr = (wid & 3) * 16;
    int jbase = (wid >> 2) * 32;

    const float* khb = g_kh + (size_t)bh * Sq * DKq;
    const float* qhb = g_qh + (size_t)bh * Sq * DKq;

    // fill As (row-major, stride 68), once
#pragma unroll
    for (int p = 0; p < 4; p++) {
        int f = tid + 256 * p;
        int r = f >> 4, dq = (f & 15) * 4;
        *(float4*)&As[r * 68 + dq] = *(const float4*)(khb + (size_t)(i0 + r) * 64 + dq);
    }

    float tv[NC]; int ti[NC];
#pragma unroll
    for (int q = 0; q < NC; q++) { tv[q] = -1.0f; ti[q] = 0; }

    int row = tid >> 2, part = tid & 3;   // topk: 4 threads/row, 16 cols each

    const unsigned* Ah = (const unsigned*)As;
    const unsigned* Bh = (const unsigned*)Bs;

    for (int j0 = 0; j0 < Sq; j0 += 64) {
        __syncthreads();
        // copy B tile (global -> shared, direct)
#pragma unroll
        for (int p = 0; p < 4; p++) {
            int f = tid + 256 * p;
            int r = f >> 4, dq = (f & 15) * 4;
            *(float4*)&Bs[r * 68 + dq] =
                *(const float4*)(qhb + (size_t)(j0 + r) * 64 + dq);
        }
        __syncthreads();

        float c[4][4];
#pragma unroll
        for (int jc = 0; jc < 4; jc++)
#pragma unroll
            for (int u = 0; u < 4; u++) c[jc][u] = 0.0f;

#pragma unroll
        for (int kc = 0; kc < 8; kc++) {
            int ao = (wr + g) * 68 + kc * 8 + t4;
            unsigned ah0 = Ah[ao], ah1 = Ah[ao + 544], ah2 = Ah[ao + 4], ah3 = Ah[ao + 548];
#pragma unroll
            for (int jc = 0; jc < 4; jc++) {
                int bo = (jbase + jc * 8 + g) * 68 + kc * 8 + t4;
                unsigned bh0 = Bh[bo], bh1 = Bh[bo + 4];
                MMA_TF32(c[jc], ah0, ah1, ah2, ah3, bh0, bh1);
            }
        }

        // write ReLU'd tile to Ss
#pragma unroll
        for (int jc = 0; jc < 4; jc++) {
            int col = jbase + jc * 8 + 2 * t4;
            int rr  = wr + g;
            float2 s0, s1;
            s0.x = fmaxf(c[jc][0], 0.0f); s0.y = fmaxf(c[jc][1], 0.0f);
            s1.x = fmaxf(c[jc][2], 0.0f); s1.y = fmaxf(c[jc][3], 0.0f);
            *(float2*)&Ss[rr * 68 + col]       = s0;
            *(float2*)&Ss[(rr + 8) * 68 + col] = s1;
        }
        __syncthreads();

        // streaming top-12 (approx): this thread covers cols [part*16, +16)
#pragma unroll
        for (int t = 0; t < 4; t++) {
            float4 v4 = *(const float4*)&Ss[row * 68 + part * 16 + t * 4];
            int cb = j0 + part * 16 + t * 4;
            float vv[4] = {v4.x, v4.y, v4.z, v4.w};
#pragma unroll
            for (int u = 0; u < 4; u++) {
                float v = vv[u];
                if (v > tv[NC - 1]) {
                    tv[NC - 1] = v; ti[NC - 1] = cb + u;
#pragma unroll
                    for (int q = NC - 1; q > 0; q--) {
                        if (tv[q] > tv[q - 1]) {
                            float tf = tv[q]; tv[q] = tv[q - 1]; tv[q - 1] = tf;
                            int tt = ti[q]; ti[q] = ti[q - 1]; ti[q - 1] = tt;
                        }
                    }
                }
            }
        }
    }
    __syncthreads();

    // smem reuse: Mv [256][NC] floats @0, Mi [256][NC] ints @3072,
    //             Ci [64][NC] ints @6144, Cv [64][NC] floats @6912
    float* Mv = sm;
    int*   Mi = (int*)(sm + 3072);
    int*   Ci = (int*)(sm + 6144);
    float* Cv = sm + 6912;
#pragma unroll
    for (int q = 0; q < NC; q++) {
        Mv[tid * NC + q] = tv[q];
        Mi[tid * NC + q] = ti[q];
    }
    // stage exact fp32 kn tile into Ss region (Ss scan reads are done)
#pragma unroll
    for (int p = 0; p < 4; p++) {
        int f = tid + 256 * p;
        int r = f >> 4, dq = (f & 15) * 4;
        *(float4*)&Ss[r * 68 + dq] =
            *(const float4*)(g_k + ((size_t)bh * Sq + i0 + r) * 64 + dq);
    }
    __syncthreads();

    // merge 4 sorted approx lists -> NC candidates per row (64 threads)
    if (tid < 64) {
        int pos0 = 0, pos1 = 0, pos2 = 0, pos3 = 0;
        for (int kk = 0; kk < NC; kk++) {
            float bv = -2.0f; int bi = 0x7fffffff, bp = 0;
            {
                float v = Mv[(tid * 4 + 0) * NC + pos0]; int ix = Mi[(tid * 4 + 0) * NC + pos0];
                if (v > bv || (v == bv && ix < bi)) { bv = v; bi = ix; bp = 0; }
            }
            {
                float v = Mv[(tid * 4 + 1) * NC + pos1]; int ix = Mi[(tid * 4 + 1) * NC + pos1];
                if (v > bv || (v == bv && ix < bi)) { bv = v; bi = ix; bp = 1; }
            }
            {
                float v = Mv[(tid * 4 + 2) * NC + pos2]; int ix = Mi[(tid * 4 + 2) * NC + pos2];
                if (v > bv || (v == bv && ix < bi)) { bv = v; bi = ix; bp = 2; }
            }
            {
                float v = Mv[(tid * 4 + 3) * NC + pos3]; int ix = Mi[(tid * 4 + 3) * NC + pos3];
                if (v > bv || (v == bv && ix < bi)) { bv = v; bi = ix; bp = 3; }
            }
            Ci[tid * NC + kk] = bi;
            if (bp == 0) pos0++; else if (bp == 1) pos1++; else if (bp == 2) pos2++; else pos3++;
        }
    }
    __syncthreads();

    // exact fp32 rescore: 4 threads/row x 3 candidates each (all 256 threads)
    {
        int r = tid >> 2, p = tid & 3;
        const float* kr = &Ss[r * 68];
#pragma unroll
        for (int s2 = 0; s2 < 3; s2++) {
            int c2 = p + 4 * s2;
            int j = Ci[r * NC + c2];
            const float* qrow = g_q + ((size_t)bh * Sq + j) * 64;
            float s = 0.0f;
#pragma unroll
            for (int d = 0; d < 64; d += 4) {
                float4 qv = *(const float4*)(qrow + d);
                s = fmaf(kr[d + 0], qv.x, s);
                s = fmaf(kr[d + 1], qv.y, s);
                s = fmaf(kr[d + 2], qv.z, s);
                s = fmaf(kr[d + 3], qv.w, s);
            }
            Cv[r * NC + c2] = fmaxf(s, 0.0f);
        }
    }
    __syncthreads();

    // final top-9 selection per row (64 threads)
    if (tid < 64) {
        float vals[NC]; int cand[NC];
#pragma unroll
        for (int c2 = 0; c2 < NC; c2++) {
            vals[c2] = Cv[tid * NC + c2];
            cand[c2] = Ci[tid * NC + c2];
        }
        int obase = (bh * Sq + i0 + tid) * KN;
        for (int a = 0; a < KN; a++) {
            int best = a;
            for (int c2 = a + 1; c2 < NC; c2++) {
                if (vals[c2] > vals[best] ||
                    (vals[c2] == vals[best] && cand[c2] < cand[best]))
                    best = c2;
            }
            float tvv = vals[a]; vals[a] = vals[best]; vals[best] = tvv;
            int   tii = cand[a]; cand[a] = cand[best]; cand[best] = tii;
            g_idx[obase + a] = cand[a];
        }
    }
}

// ---------------- prep: transpose conv_w [o][c][kk] -> Wt[kk][c][o] ---------
__global__ void transpose_convw_kernel(const float* __restrict__ w)
{
    int t = blockIdx.x * 256 + threadIdx.x;
    if (t < KN * DKq * DKq) {
        int o = t & 63, c = (t >> 6) & 63, kk = t >> 12;
        g_wt[t] = w[(o * 64 + c) * KN + kk];
    }
}

// ---------------- Kernel D: gather v by idx + grouped conv, scatter to y^T --
__global__ __launch_bounds__(128, 2) void conv_kernel(const float* __restrict__ convb)
{
    extern __shared__ float smd[];
    float* v_s  = smd;                   // [288][64]
    float* w_s  = smd + 288 * 64;        // [64 c][64 o]
    int*   sidx = (int*)(smd + 288 * 64 + 4096);  // [288]

    int bh = blockIdx.y;
    int i0 = blockIdx.x * 32;
    int b  = bh >> 3, h = bh & 7;
    int tid = threadIdx.x;

    for (int t = tid; t < 288; t += 128)
        sidx[t] = g_idx[(bh * Sq + i0 + t / KN) * KN + (t % KN)];

    float4 wreg[8];
#pragma unroll
    for (int p = 0; p < 8; p++)
        wreg[p] = *(const float4*)(g_wt + (tid + 128 * p) * 4);

    __syncthreads();

    const float* vbase = g_v + (size_t)bh * Sq * DKq;
    for (int p = 0; p < 36; p++) {
        int f = tid + 128 * p;
        int r = f >> 4, fq = (f & 15) * 4;
        int j = sidx[r];
        float4 vv = *(const float4*)(vbase + (size_t)j * 64 + fq);
        *(float4*)&v_s[r * 64 + fq] = vv;
    }

    int og = tid & 15; int o0 = og * 4;
    int ig = tid >> 4;
    ull acc[4][2];
#pragma unroll
    for (int t = 0; t < 4; t++) { acc[t][0] = 0ULL; acc[t][1] = 0ULL; }

    for (int kk = 0; kk < KN; kk++) {
        __syncthreads();
#pragma unroll
        for (int p = 0; p < 8; p++)
            *(float4*)&w_s[(tid + 128 * p) * 4] = wreg[p];
        __syncthreads();
        if (kk + 1 < KN) {
#pragma unroll
            for (int p = 0; p < 8; p++)
                wreg[p] = *(const float4*)(g_wt + (kk + 1) * 4096 + (tid + 128 * p) * 4);
        }
#pragma unroll 4
        for (int c = 0; c < 64; c++) {
            ulonglong2 wp = *(const ulonglong2*)&w_s[c * 64 + o0];
#pragma unroll
            for (int t = 0; t < 4; t++) {
                ull v2 = pack2(v_s[(((ig * 4 + t) * KN) + kk) * 64 + c]);
                fma2(acc[t][0], v2, wp.x);
                fma2(acc[t][1], v2, wp.y);
            }
        }
    }

    float4 cb = *(const float4*)(convb + o0);
    int colbase = (h * 64 + (i0 >> 5)) * Mq + b * Sq;
#pragma unroll
    for (int t = 0; t < 4; t++) {
        int il = ig * 4 + t;
        int sp = ((i0 + il) & 31) * 64 + o0;
        float4 o;
        o.x = lo32(acc[t][0]) + cb.x;
        o.y = hi32(acc[t][0]) + cb.y;
        o.z = lo32(acc[t][1]) + cb.z;
        o.w = hi32(acc[t][1]) + cb.w;
        *(float4*)&g_y[colbase + sp] = o;
    }
}

// ---------------- Kernel E: final = y @ Wo^T + b ----------------------------
__global__ __launch_bounds__(256, 2) void out_gemm_kernel(
    const float* __restrict__ Wo, const float* __restrict__ bo,
    float* __restrict__ outp)
{
    __shared__ __align__(16) float As[16][132];
    __shared__ __align__(16) float Bs[16][132];

    int m0 = blockIdx.y * 128, n0 = blockIdx.x * 128;
    int tid = threadIdx.x, tx = tid & 15, ty = tid >> 4;
    int r0 = ty * 8, c0 = tx * 8;

    ull acc[4][8];
#pragma unroll
    for (int i = 0; i < 4; i++)
#pragma unroll
        for (int j = 0; j < 8; j++) acc[i][j] = 0ULL;

    int lrow = tid >> 2, lk = (tid & 3) * 4;
    int fk = tid >> 5, fm = tid & 31;

    const float* pa0 = g_y + (size_t)fk * Mq + m0 + fm * 4;
    const float* pa1 = g_y + (size_t)(fk + 8) * Mq + m0 + fm * 4;
    const float* pb0 = Wo + (size_t)(n0 + lrow)      * 512 + lk;
    const float* pb1 = Wo + (size_t)(n0 + lrow + 64) * 512 + lk;

    float4 a0 = *(const float4*)(pa0);
    float4 a1 = *(const float4*)(pa1);
    float4 b0 = *(const float4*)(pb0);
    float4 b1 = *(const float4*)(pb1);

    for (int k0 = 0; k0 < 512; k0 += 16) {
        __syncthreads();
        *(float4*)&As[fk][fm * 4]     = a0;
        *(float4*)&As[fk + 8][fm * 4] = a1;
        Bs[lk+0][lrow] = b0.x; Bs[lk+1][lrow] = b0.y; Bs[lk+2][lrow] = b0.z; Bs[lk+3][lrow] = b0.w;
        Bs[lk+0][lrow+64] = b1.x; Bs[lk+1][lrow+64] = b1.y; Bs[lk+2][lrow+64] = b1.z; Bs[lk+3][lrow+64] = b1.w;
        __syncthreads();
        if (k0 + 16 < 512) {
            a0 = *(const float4*)(pa0 + (size_t)(k0 + 16) * Mq);
            a1 = *(const float4*)(pa1 + (size_t)(k0 + 16) * Mq);
            b0 = *(const float4*)(pb0 + k0 + 16);
            b1 = *(const float4*)(pb1 + k0 + 16);
        }
#pragma unroll
        for (int kk = 0; kk < 16; kk++) {
            ulonglong2 ap0 = *(const ulonglong2*)&As[kk][r0];
            ulonglong2 ap1 = *(const ulonglong2*)&As[kk][r0 + 4];
            float4 bv0 = *(const float4*)&Bs[kk][c0];
            float4 bv1 = *(const float4*)&Bs[kk][c0 + 4];
            ull b2[8];
            b2[0] = pack2(bv0.x); b2[1] = pack2(bv0.y); b2[2] = pack2(bv0.z); b2[3] = pack2(bv0.w);
            b2[4] = pack2(bv1.x); b2[5] = pack2(bv1.y); b2[6] = pack2(bv1.z); b2[7] = pack2(bv1.w);
            ull a2[4] = {ap0.x, ap0.y, ap1.x, ap1.y};
#pragma unroll
            for (int i = 0; i < 4; i++)
#pragma unroll
                for (int j = 0; j < 8; j++) fma2(acc[i][j], a2[i], b2[j]);
        }
    }

    float4 bias0 = *(const float4*)(bo + n0 + c0);
    float4 bias1 = *(const float4*)(bo + n0 + c0 + 4);
#pragma unroll
    for (int i = 0; i < 4; i++) {
#pragma unroll
        for (int half = 0; half < 2; half++) {
            int m = m0 + r0 + 2 * i + half;
            float4 o0, o1;
            if (half == 0) {
                o0.x = lo32(acc[i][0]) + bias0.x; o0.y = lo32(acc[i][1]) + bias0.y;
                o0.z = lo32(acc[i][2]) + bias0.z; o0.w = lo32(acc[i][3]) + bias0.w;
                o1.x = lo32(acc[i][4]) + bias1.x; o1.y = lo32(acc[i][5]) + bias1.y;
                o1.z = lo32(acc[i][6]) + bias1.z; o1.w = lo32(acc[i][7]) + bias1.w;
            } else {
                o0.x = hi32(acc[i][0]) + bias0.x; o0.y = hi32(acc[i][1]) + bias0.y;
                o0.z = hi32(acc[i][2]) + bias0.z; o0.w = hi32(acc[i][3]) + bias0.w;
                o1.x = hi32(acc[i][4]) + bias1.x; o1.y = hi32(acc[i][5]) + bias1.y;
                o1.z = hi32(acc[i][6]) + bias1.z; o1.w = hi32(acc[i][7]) + bias1.w;
            }
            float* po = outp + (size_t)m * 512 + n0 + c0;
            *(float4*)po = o0;
            *(float4*)(po + 4) = o1;
        }
    }
}

// ---------------- launch -----------------------------------------------------
extern "C" void kernel_launch(void* const* d_in, const int* in_sizes, int n_in,
                              void* d_out, int out_size)
{
    (void)in_sizes; (void)n_in; (void)out_size;
    const float* x      = (const float*)d_in[0];
    const float* Wq_w   = (const float*)d_in[1];
    const float* Wq_b   = (const float*)d_in[2];
    const float* Wk_w   = (const float*)d_in[3];
    const float* Wk_b   = (const float*)d_in[4];
    const float* Wv_w   = (const float*)d_in[5];
    const float* Wv_b   = (const float*)d_in[6];
    const float* Wo_w   = (const float*)d_in[7];
    const float* Wo_b   = (const float*)d_in[8];
    const float* conv_w = (const float*)d_in[9];
    const float* conv_b = (const float*)d_in[10];
    float* outp = (float*)d_out;

    const int SMEM_C = 13056 * 4;                            // 52224 B
    const int SMEM_D = (288 * 64 + 64 * 64) * 4 + 288 * 4;   // 91264 B
    cudaFuncSetAttribute(sim_topk_kernel, cudaFuncAttributeMaxDynamicSharedMemorySize, SMEM_C);
    cudaFuncSetAttribute(conv_kernel,     cudaFuncAttributeMaxDynamicSharedMemorySize, SMEM_D);

    qkv_gemm_kernel<<<dim3(4, 64, 3), 256>>>(x, Wq_w, Wq_b, Wk_w, Wk_b, Wv_w, Wv_b);
    normalize_split_kernel<<<16384, 256>>>();
    transpose_convw_kernel<<<144, 256>>>(conv_w);
    sim_topk_kernel<<<dim3(32, 32), 256, SMEM_C>>>();
    conv_kernel<<<dim3(64, 32), 128, SMEM_D>>>(conv_b);
    out_gemm_kernel<<<dim3(4, 64), 256>>>(Wo_w, Wo_b, outp);
}